// round 17
// baseline (speedup 1.0000x reference)
#include <cuda_runtime.h>
#include <cuda_bf16.h>
#include <cstdint>
#include <math.h>

#define B     64
#define T     256
#define U     1024
#define G3    3072
#define NBLK  128
#define NT    512
#define STAGGER_CYC 3072ULL

// h packed in MMA A-fragment order:
// [par][ ((bt*64 + kk)*2 + half)*32 + lane ] -> uint4
__device__ __align__(16) uint4 g_hpk[2][4 * 64 * 2 * 32];
// flags[kq][bth]: 16 counters, 128B apart (one L2 line each)
__device__ __align__(128) unsigned g_flag[16 * 32];
__device__ unsigned g_bar_cnt, g_bar_gen;

// ---- SMEM layout (bytes) ----
#define SM_W      0
#define W_NSTR    2064
#define W_PSTR    49536
#define SM_REC    99072              // [2 group][8 plane][32 row][26 f]
#define REC_GRP   26624              // bytes per group region
#define REC_PL    832                // floats per plane (32*26)
#define SMEM_TOTAL (99072 + 2*26624) // 152320

// ---- PTX helpers ----
__device__ __forceinline__ uint32_t smem_u32(const void* p) {
    uint32_t a;
    asm("{ .reg .u64 t; cvta.to.shared.u64 t, %1; cvt.u32.u64 %0, t; }" : "=r"(a) : "l"(p));
    return a;
}
__device__ __forceinline__ void ldsm2(uint32_t* r, uint32_t addr) {
    asm volatile("ldmatrix.sync.aligned.m8n8.x2.shared.b16 {%0,%1}, [%2];"
                 : "=r"(r[0]), "=r"(r[1]) : "r"(addr));
}
__device__ __forceinline__ void ldsm4(uint32_t* r, uint32_t addr) {
    asm volatile("ldmatrix.sync.aligned.m8n8.x4.shared.b16 {%0,%1,%2,%3}, [%4];"
                 : "=r"(r[0]), "=r"(r[1]), "=r"(r[2]), "=r"(r[3]) : "r"(addr));
}
__device__ __forceinline__ void mma4(float* c, const uint4& a, uint32_t b0, uint32_t b1) {
    asm volatile("mma.sync.aligned.m16n8k16.row.col.f32.bf16.bf16.f32 "
                 "{%0,%1,%2,%3}, {%4,%5,%6,%7}, {%8,%9}, {%0,%1,%2,%3};"
                 : "+f"(c[0]), "+f"(c[1]), "+f"(c[2]), "+f"(c[3])
                 : "r"(a.x), "r"(a.y), "r"(a.z), "r"(a.w), "r"(b0), "r"(b1));
}
__device__ __forceinline__ void wait_flag(unsigned* f, unsigned tgt) {
    unsigned g;
    while (1) {
        asm volatile("ld.acquire.gpu.u32 %0, [%1];" : "=r"(g) : "l"(f));
        if ((int)(g - tgt) >= 0) break;
        __nanosleep(16);
    }
}
__device__ __forceinline__ void arrive_flag(unsigned* f) {
    asm volatile("red.release.gpu.global.add.u32 [%0], 1;" :: "l"(f));
}
__device__ __forceinline__ void grid_barrier() {
    __syncthreads();
    if (threadIdx.x == 0) {
        unsigned gen0;
        asm volatile("ld.acquire.gpu.u32 %0, [%1];" : "=r"(gen0) : "l"(&g_bar_gen));
        unsigned prev;
        asm volatile("atom.release.gpu.global.add.u32 %0, [%1], 1;" : "=r"(prev) : "l"(&g_bar_cnt));
        if (prev == NBLK - 1) {
            asm volatile("st.relaxed.gpu.global.u32 [%0], 0;" :: "l"(&g_bar_cnt));
            asm volatile("red.release.gpu.global.add.u32 [%0], 1;" :: "l"(&g_bar_gen));
        } else {
            unsigned g;
            do { asm volatile("ld.acquire.gpu.u32 %0, [%1];" : "=r"(g) : "l"(&g_bar_gen)); } while (g == gen0);
        }
    }
    __syncthreads();
}

// pack one unit (b, u0+uu): hi at poff, lo at poff+512 (R13-verified layout)
__device__ __forceinline__ void pack_unit(char* bufbase, uint32_t off, float v) {
    __nv_bfloat16 h = __float2bfloat16(v);
    __nv_bfloat16 lo = __float2bfloat16(v - __bfloat162float(h));
    *(unsigned short*)(bufbase + off)       = __bfloat16_as_ushort(h);
    *(unsigned short*)(bufbase + off + 512) = __bfloat16_as_ushort(lo);
}

__global__ void __launch_bounds__(NT, 1)
gru_all(const int* __restrict__ x, const float* __restrict__ hidden,
        const float* __restrict__ Win, const float* __restrict__ Wrec,
        const float* __restrict__ bin, const float* __restrict__ brec,
        float* __restrict__ out) {
    extern __shared__ __align__(1024) char smem[];
    const uint32_t sbase = smem_u32(smem);
    const int tid = threadIdx.x;
    const int wid = tid >> 5;
    const int l   = tid & 31;
    const int blk = blockIdx.x;
    const int u0  = blk * 8;

    // ---- one-time: W_rec slice -> bf16 hi/lo in SMEM [pass][n][k] ----
    for (int idx = tid; idx < 24 * U; idx += NT) {
        int k = idx / 24;
        int j = idx - k * 24;
        int gate = j >> 3, uu = j & 7;
        float w = Wrec[(size_t)k * G3 + gate * U + u0 + uu];
        __nv_bfloat16 hi = __float2bfloat16(w);
        __nv_bfloat16 lo = __float2bfloat16(w - __bfloat162float(hi));
        *(__nv_bfloat16*)(smem + SM_W + j * W_NSTR + k * 2) = hi;
        *(__nv_bfloat16*)(smem + SM_W + W_PSTR + j * W_NSTR + k * 2) = lo;
    }

    // ---- gate mapping: 512 threads, 1 unit each: (b = tid>>3, uu) ----
    const int b   = tid >> 3;
    const int uu  = tid & 7;
    const int bth = tid >> 8;            // group id (gate side)
    const int btg = b >> 4, r_ = b & 15;
    const int kk_self = u0 >> 4;
    const uint32_t woff = (uint32_t)((r_ & 7) * 4 + ((uu >> 1) & 3)) * 16
                        + (uint32_t)((r_ >> 3) + 2 * ((u0 >> 3) & 1)) * 4
                        + (uu & 1) * 2;
    const uint32_t poff = (uint32_t)((btg * 64 + kk_self) * 2) * 512 + woff;

    const float cz  = bin[0 * U + u0 + uu] + brec[0 * U + u0 + uu];
    const float cr  = bin[1 * U + u0 + uu] + brec[1 * U + u0 + uu];
    const float bih = bin[2 * U + u0 + uu];
    const float bhh = brec[2 * U + u0 + uu];
    float hold = hidden[(size_t)b * U + u0 + uu];
    int tok = x[b * T];

    // ---- warp MMA mapping: group = wid>>3, kq = wid&7 ----
    const int kq = wid & 7;
    const uint32_t boff4 = (uint32_t)((l >> 4) * 8 + (l & 7)) * W_NSTR + ((l >> 3) & 1) * 16;
    const uint32_t boff2 = (uint32_t)(l & 7) * W_NSTR + (l & 8) * 2;
    const int grp = blk >> 4;                 // producer k-eighth
    const int fc  = kq * 2 + bth;             // consumer flag index
    const int fp  = grp * 2 + bth;            // producer flag index
    float* recg = (float*)(smem + SM_REC + bth * REC_GRP);

    unsigned fbase = *(volatile unsigned*)&g_flag[fc * 32];
    grid_barrier();

    // publish h0 into buffer 0; per-group arrival
    pack_unit((char*)g_hpk[0], poff, hold);
    grid_barrier();   // race-free init for step 0 (one-time cost)
    if (tid == 0)   arrive_flag(&g_flag[(grp * 2 + 0) * 32]);
    if (tid == 256) arrive_flag(&g_flag[(grp * 2 + 1) * 32]);

    // ---- phase stagger: group 1 starts ~3K cycles late (scheduling only;
    //      work and output identical). Keeps the two pipelines in antiphase
    //      so each group's GEMM hides the other's wait/gate tail. ----
    if (bth == 1) {
        unsigned long long s0 = clock64();
        while (clock64() - s0 < STAGGER_CYC) { }
    }

    for (int t = 0; t < T; t++) {
        const int par = t & 1;

        // gate-input loads issued before the flag wait
        const float* wrow = Win + (size_t)tok * G3 + u0 + uu;
        float xz = wrow[0], xr = wrow[U], xh = wrow[2 * U];
        int tok_n = (t + 1 < T) ? x[b * T + t + 1] : 0;

        // wait for the 16 producer CTAs of (this k-eighth, this group)
        if (l == 0) wait_flag(&g_flag[fc * 32], fbase + 16u * (t + 1));
        __syncwarp();

        // ---- GEMM: 8 k-tiles, 2 batch-tiles of this group ----
        float acc[2][3][4];
        #pragma unroll
        for (int bt = 0; bt < 2; bt++)
            #pragma unroll
            for (int nt = 0; nt < 3; nt++)
                #pragma unroll
                for (int e = 0; e < 4; e++) acc[bt][nt][e] = 0.f;

        const uint4* pA0 = g_hpk[par] + (size_t)(((2 * bth)     * 64 + kq * 8) * 2) * 32 + l;
        const uint4* pA1 = g_hpk[par] + (size_t)(((2 * bth + 1) * 64 + kq * 8) * 2) * 32 + l;

        uint4 Ah[2][2], Al[2][2];
        #pragma unroll
        for (int i = 0; i < 2; i++) {
            Ah[0][i] = __ldcg(pA0 + i * 64); Al[0][i] = __ldcg(pA0 + i * 64 + 32);
            Ah[1][i] = __ldcg(pA1 + i * 64); Al[1][i] = __ldcg(pA1 + i * 64 + 32);
        }

        #pragma unroll
        for (int kt = 0; kt < 8; kt++) {
            uint32_t wb = sbase + SM_W + (uint32_t)(kq * 8 + kt) * 32;
            uint32_t bh01[4], bl01[4], bh2[2], bl2[2];
            ldsm4(bh01, wb + boff4);
            ldsm2(bh2,  wb + 16 * W_NSTR + boff2);
            ldsm4(bl01, wb + W_PSTR + boff4);
            ldsm2(bl2,  wb + W_PSTR + 16 * W_NSTR + boff2);

            uint4 c0h = Ah[0][kt & 1], c0l = Al[0][kt & 1];
            uint4 c1h = Ah[1][kt & 1], c1l = Al[1][kt & 1];
            if (kt < 6) {
                Ah[0][kt & 1] = __ldcg(pA0 + (kt + 2) * 64);
                Al[0][kt & 1] = __ldcg(pA0 + (kt + 2) * 64 + 32);
                Ah[1][kt & 1] = __ldcg(pA1 + (kt + 2) * 64);
                Al[1][kt & 1] = __ldcg(pA1 + (kt + 2) * 64 + 32);
            }

            mma4(acc[0][0], c0h, bh01[0], bh01[1]);
            mma4(acc[0][1], c0h, bh01[2], bh01[3]);
            mma4(acc[0][2], c0h, bh2[0],  bh2[1]);
            mma4(acc[1][0], c1h, bh01[0], bh01[1]);
            mma4(acc[1][1], c1h, bh01[2], bh01[3]);
            mma4(acc[1][2], c1h, bh2[0],  bh2[1]);

            mma4(acc[0][0], c0h, bl01[0], bl01[1]);
            mma4(acc[0][1], c0h, bl01[2], bl01[3]);
            mma4(acc[0][2], c0h, bl2[0],  bl2[1]);
            mma4(acc[1][0], c1h, bl01[0], bl01[1]);
            mma4(acc[1][1], c1h, bl01[2], bl01[3]);
            mma4(acc[1][2], c1h, bl2[0],  bl2[1]);

            mma4(acc[0][0], c0l, bh01[0], bh01[1]);
            mma4(acc[0][1], c0l, bh01[2], bh01[3]);
            mma4(acc[0][2], c0l, bh2[0],  bh2[1]);
            mma4(acc[1][0], c1l, bh01[0], bh01[1]);
            mma4(acc[1][1], c1l, bh01[2], bh01[3]);
            mma4(acc[1][2], c1l, bh2[0],  bh2[1]);
        }

        // ---- epilogue: partials -> this group's plane kq ----
        {
            float* pl = recg + kq * REC_PL;
            int row = l >> 2, c2 = (l & 3) * 2;
            #pragma unroll
            for (int bt = 0; bt < 2; bt++) {
                int bb0 = bt * 16 + row;   // group-local row 0..31
                #pragma unroll
                for (int nt = 0; nt < 3; nt++) {
                    int j0 = nt * 8 + c2;
                    *(float2*)&pl[bb0 * 26 + j0]       = make_float2(acc[bt][nt][0], acc[bt][nt][1]);
                    *(float2*)&pl[(bb0 + 8) * 26 + j0] = make_float2(acc[bt][nt][2], acc[bt][nt][3]);
                }
            }
        }
        // group-local barrier (256 threads, id 1 or 2)
        if (bth == 0) asm volatile("bar.sync 1, 256;" ::: "memory");
        else          asm volatile("bar.sync 2, 256;" ::: "memory");

        // ---- gates: 1 unit per thread (group-local rows) ----
        {
            float rz = cz, rr = cr, rh = bhh;
            const int lb = b & 31;
            #pragma unroll
            for (int p = 0; p < 8; p++) {
                const float* pl = recg + p * REC_PL + lb * 26;
                rz += pl[uu];
                rr += pl[8 + uu];
                rh += pl[16 + uu];
            }
            float z  = __fdividef(1.f, 1.f + __expf(-(xz + rz)));
            float r  = __fdividef(1.f, 1.f + __expf(-(xr + rr)));
            float ta = xh + bih + r * rh;
            float hh = 1.f - __fdividef(2.f, __expf(2.f * ta) + 1.f);
            float hn = z * hold + (1.f - z) * hh;
            hold = hn;
            pack_unit((char*)g_hpk[par ^ 1], poff, hn);
            // group-local barrier: all packs done + plane reads done
            if (bth == 0) asm volatile("bar.sync 1, 256;" ::: "memory");
            else          asm volatile("bar.sync 2, 256;" ::: "memory");
            if ((tid == 0 || tid == 256) && t < T - 1)
                arrive_flag(&g_flag[fp * 32]);
            out[((size_t)b * T + t) * U + u0 + uu] = hn;
            if (t == T - 1)
                out[(size_t)B * T * U + (size_t)b * U + u0 + uu] = hn;
            tok = tok_n;
        }
    }
}

extern "C" void kernel_launch(void* const* d_in, const int* in_sizes, int n_in,
                              void* d_out, int out_size) {
    const int*   x      = (const int*)d_in[0];
    const float* hidden = (const float*)d_in[1];
    const float* Win    = (const float*)d_in[2];
    const float* Wrec   = (const float*)d_in[3];
    const float* bin    = (const float*)d_in[4];
    const float* brec   = (const float*)d_in[5];
    float* out = (float*)d_out;

    cudaFuncSetAttribute(gru_all, cudaFuncAttributeMaxDynamicSharedMemorySize, SMEM_TOTAL);
    gru_all<<<NBLK, NT, SMEM_TOTAL>>>(x, hidden, Win, Wrec, bin, brec, out);
}